// round 4
// baseline (speedup 1.0000x reference)
#include <cuda_runtime.h>
#include <cstdint>

// LDPC BP over this fixed H reduces, on the hard-decision output, to
//   out = (llr > 0) ? 0 : 1.
//
// Proof (fp32-safe):
//  - every c2v entry written by the check sweep is 2*atan(exp(z)) with
//    z = 0.5*(s - v2c) in [-0.5, ~3.7]  (s = sum of <=2 c2v values, each in
//    (0, pi); |v2c| <= 1 always since each v2c update is sign * product of
//    tanh with |tanh| < 1, init 1.0), so no under/overflow and every c2v
//    entry is strictly positive after iteration 1 (rows written in full);
//  - soft = sign(llr) * prod_{r<4} tanh(0.5*c2v[r]) = sign(llr)*(positive);
//  - hence where(soft > 0, 0, 1) == where(llr > 0, 0, 1) elementwise.
//
// R1-R3 all failed with rel_err EXACTLY 1.000000e+00 while writing provably
// correct decision bits as int32. The only mechanism consistent with that
// exactness: the harness's __output__ dtype is float32, so int 0/1 bit
// patterns are reinterpreted as float denormals (~1e-45 ~ 0), making
// ||ref - mine||/||ref|| == 1 - O(1e-45) -> prints exactly 1.0.
// Fix: emit float32 0.0f / 1.0f.

#define LDPC_N_ELEMS 917504  // 131072 * 7, fixed by the problem definition
#define LDPC_N4      (LDPC_N_ELEMS / 4)  // 229376, exact

__global__ void ldpc_sign_kernel_f4(const float4* __restrict__ llr4,
                                    float4* __restrict__ out4) {
    int i = blockIdx.x * blockDim.x + threadIdx.x;
    if (i < LDPC_N4) {
        float4 v = llr4[i];
        float4 o;
        o.x = (v.x > 0.0f) ? 0.0f : 1.0f;
        o.y = (v.y > 0.0f) ? 0.0f : 1.0f;
        o.z = (v.z > 0.0f) ? 0.0f : 1.0f;
        o.w = (v.w > 0.0f) ? 0.0f : 1.0f;
        out4[i] = o;
    }
}

extern "C" void kernel_launch(void* const* d_in, const int* in_sizes, int n_in,
                              void* d_out, int out_size) {
    // llr is by far the largest input (917504 f32 vs H's 28 i32), under any
    // denomination of in_sizes (bytes or elements).
    int best = 0;
    for (int i = 1; i < n_in; ++i) {
        if (in_sizes[i] > in_sizes[best]) best = i;
    }
    const float4* llr4 = (const float4*)d_in[best];
    float4* out4 = (float4*)d_out;

    const int threads = 256;
    const int blocks = (LDPC_N4 + threads - 1) / threads;  // 896
    ldpc_sign_kernel_f4<<<blocks, threads>>>(llr4, out4);
}